// round 8
// baseline (speedup 1.0000x reference)
#include <cuda_runtime.h>

#define T_LEN 512
#define HH    50
#define G4    200      // 4*H gates
#define GB    16       // batch rows per CTA
#define NTHR  416      // 13 warps; 400 active in matvec
#define NACT  400      // 50 gate-chunks * 8 batch-groups
#define NCTA  128      // 2048 / GB

// shared layout (float offsets, all 16B-aligned)
#define OFF_W0T   0        // [50][200]   Whh0^T
#define OFF_WCT   10000    // [100][200]  [Wih1;Whh1]^T
#define OFF_WIH0  30000    // [200]
#define OFF_B0    30200    // [200]
#define OFF_B1    30400    // [200]
#define OFF_HD    30600    // [100][16] float2 (h,h) duplicated -> 3200 floats
#define OFF_C1    33800    // [50][16]
#define OFF_C2    34600    // [50][16]
#define OFF_GBUF  35400    // [200][18]  (stride 18: avoids STS.64 bank conflicts)
#define OFF_XSD   39000    // [512][16] float2 (x,x) duplicated -> 16384 floats
#define SMEM_FLOATS 55384
#define SMEM_BYTES  (SMEM_FLOATS * 4)

typedef unsigned long long ull;

// packed fp32x2 fma: d = a*b + d  (exact fp32 per lane)
#define FFMA2(d, a, b) \
    asm("fma.rn.f32x2 %0, %1, %2, %0;" : "+l"(d) : "l"(a), "l"(b))

#define UNPACK2(lo, hi, v) \
    asm("mov.b64 {%0, %1}, %2;" : "=f"(lo), "=f"(hi) : "l"(v))

__device__ __forceinline__ float sigf(float x) {
    return __fdividef(1.f, 1.f + __expf(-x));
}
__device__ __forceinline__ float tanh_fast(float x) {
    return fmaf(2.f, __fdividef(1.f, 1.f + __expf(-2.f * x)), -1.f);
}

extern __shared__ float sm[];

__global__ __launch_bounds__(NTHR, 1)
void lstm2_kernel(const float* __restrict__ x,
                  const float* __restrict__ Wih0, const float* __restrict__ Whh0,
                  const float* __restrict__ bih0, const float* __restrict__ bhh0,
                  const float* __restrict__ Wih1, const float* __restrict__ Whh1,
                  const float* __restrict__ bih1, const float* __restrict__ bhh1,
                  const float* __restrict__ Wfc,  const float* __restrict__ bfc,
                  float* __restrict__ out)
{
    float* W0T   = sm + OFF_W0T;
    float* WcT   = sm + OFF_WCT;
    float* wih0  = sm + OFF_WIH0;
    float* bias0 = sm + OFF_B0;
    float* bias1 = sm + OFF_B1;
    float* hd    = sm + OFF_HD;
    float* c1s   = sm + OFF_C1;
    float* c2s   = sm + OFF_C2;
    float* gbuf  = sm + OFF_GBUF;
    float* xsd   = sm + OFF_XSD;

    const int tid = threadIdx.x;
    const int b0  = blockIdx.x * GB;

    // ---- stage weights (transposed: gate index contiguous) ----
    for (int i = tid; i < G4 * HH; i += NTHR) {
        int j = i / HH, k = i % HH;
        W0T[k * G4 + j]        = Whh0[i];
        WcT[k * G4 + j]        = Wih1[i];
        WcT[(HH + k) * G4 + j] = Whh1[i];
    }
    for (int i = tid; i < G4; i += NTHR) {
        wih0[i]  = Wih0[i];
        bias0[i] = bih0[i] + bhh0[i];
        bias1[i] = bih1[i] + bhh1[i];
    }
    for (int i = tid; i < 100 * GB * 2; i += NTHR) hd[i] = 0.f;
    for (int i = tid; i < HH * GB; i += NTHR) { c1s[i] = 0.f; c2s[i] = 0.f; }
    // stage x duplicated: xsd[(t*16+b)*2 + {0,1}] = x[b0+b][t]
    for (int i = tid; i < GB * T_LEN; i += NTHR) {
        int t = i >> 4, b = i & 15;
        float v = x[(b0 + b) * T_LEN + t];
        xsd[i * 2]     = v;
        xsd[i * 2 + 1] = v;
    }
    __syncthreads();

    const int c  = tid >> 3;   // gate chunk 0..49 (4 gates each)
    const int bg = tid & 7;    // batch pair-group 0..7 (batch rows 2bg, 2bg+1)
    const bool act = (tid < NACT);

    // hoisted invariant pairs
    ull w0x = 0, w0y = 0, b0x = 0, b0y = 0, b1x = 0, b1y = 0;
    if (act) {
        ulonglong2 t0 = *(const ulonglong2*)(wih0  + 4 * c); w0x = t0.x; w0y = t0.y;
        ulonglong2 t1 = *(const ulonglong2*)(bias0 + 4 * c); b0x = t1.x; b0y = t1.y;
        ulonglong2 t2 = *(const ulonglong2*)(bias1 + 4 * c); b1x = t2.x; b1y = t2.y;
    }

    for (int t = 0; t < T_LEN; ++t) {
        // ================= layer 0 gates =================
        if (act) {
            ulonglong2 xp = *(const ulonglong2*)(xsd + t * 32 + 4 * bg);
            ull a0A = b0x, a0B = b0y, a1A = b0x, a1B = b0y;
            FFMA2(a0A, w0x, xp.x); FFMA2(a0B, w0y, xp.x);
            FFMA2(a1A, w0x, xp.y); FFMA2(a1B, w0y, xp.y);

            #pragma unroll 5
            for (int k = 0; k < HH; ++k) {
                ulonglong2 wv = *(const ulonglong2*)(W0T + k * G4 + 4 * c);
                ulonglong2 hp = *(const ulonglong2*)(hd + k * 32 + 4 * bg);
                FFMA2(a0A, wv.x, hp.x); FFMA2(a0B, wv.y, hp.x);
                FFMA2(a1A, wv.x, hp.y); FFMA2(a1B, wv.y, hp.y);
            }
            float g0[4], g1[4];
            UNPACK2(g0[0], g0[1], a0A); UNPACK2(g0[2], g0[3], a0B);
            UNPACK2(g1[0], g1[1], a1A); UNPACK2(g1[2], g1[3], a1B);
            #pragma unroll
            for (int q = 0; q < 4; ++q)
                *(float2*)(gbuf + (4 * c + q) * 18 + 2 * bg) = make_float2(g0[q], g1[q]);
        }
        __syncthreads();

        // ================= layer 0 elementwise =================
        for (int i = tid; i < HH * GB; i += NTHR) {
            int k = i >> 4, bb = i & 15;
            float ig = sigf(gbuf[k * 18 + bb]);
            float fg = sigf(gbuf[(HH + k) * 18 + bb]);
            float gg = tanh_fast(gbuf[(2 * HH + k) * 18 + bb]);
            float og = sigf(gbuf[(3 * HH + k) * 18 + bb]);
            float cc = fmaf(fg, c1s[k * 16 + bb], ig * gg);
            c1s[k * 16 + bb] = cc;
            float h = og * tanh_fast(cc);
            *(float2*)(hd + (k * 16 + bb) * 2) = make_float2(h, h);
        }
        __syncthreads();

        // ================= layer 1 gates (input+recurrent fused) =================
        if (act) {
            ull a0A = b1x, a0B = b1y, a1A = b1x, a1B = b1y;
            #pragma unroll 5
            for (int k = 0; k < 2 * HH; ++k) {
                ulonglong2 wv = *(const ulonglong2*)(WcT + k * G4 + 4 * c);
                ulonglong2 hp = *(const ulonglong2*)(hd + k * 32 + 4 * bg);
                FFMA2(a0A, wv.x, hp.x); FFMA2(a0B, wv.y, hp.x);
                FFMA2(a1A, wv.x, hp.y); FFMA2(a1B, wv.y, hp.y);
            }
            float g0[4], g1[4];
            UNPACK2(g0[0], g0[1], a0A); UNPACK2(g0[2], g0[3], a0B);
            UNPACK2(g1[0], g1[1], a1A); UNPACK2(g1[2], g1[3], a1B);
            #pragma unroll
            for (int q = 0; q < 4; ++q)
                *(float2*)(gbuf + (4 * c + q) * 18 + 2 * bg) = make_float2(g0[q], g1[q]);
        }
        __syncthreads();

        // ================= layer 1 elementwise =================
        for (int i = tid; i < HH * GB; i += NTHR) {
            int k = i >> 4, bb = i & 15;
            float ig = sigf(gbuf[k * 18 + bb]);
            float fg = sigf(gbuf[(HH + k) * 18 + bb]);
            float gg = tanh_fast(gbuf[(2 * HH + k) * 18 + bb]);
            float og = sigf(gbuf[(3 * HH + k) * 18 + bb]);
            float cc = fmaf(fg, c2s[k * 16 + bb], ig * gg);
            c2s[k * 16 + bb] = cc;
            float h = og * tanh_fast(cc);
            *(float2*)(hd + ((HH + k) * 16 + bb) * 2) = make_float2(h, h);
        }
        __syncthreads();
    }

    // ================= final classifier on h2[T-1] =================
    if (tid < GB * 2) {
        int bb = tid >> 1, cls = tid & 1;
        float acc = bfc[cls];
        #pragma unroll
        for (int k = 0; k < HH; ++k)
            acc = fmaf(Wfc[cls * HH + k], hd[((HH + k) * 16 + bb) * 2], acc);
        out[(b0 + bb) * 2 + cls] = acc;
    }
}

extern "C" void kernel_launch(void* const* d_in, const int* in_sizes, int n_in,
                              void* d_out, int out_size)
{
    const float* x    = (const float*)d_in[0];
    const float* Wih0 = (const float*)d_in[1];
    const float* Whh0 = (const float*)d_in[2];
    const float* bih0 = (const float*)d_in[3];
    const float* bhh0 = (const float*)d_in[4];
    const float* Wih1 = (const float*)d_in[5];
    const float* Whh1 = (const float*)d_in[6];
    const float* bih1 = (const float*)d_in[7];
    const float* bhh1 = (const float*)d_in[8];
    const float* Wfc  = (const float*)d_in[9];
    const float* bfc  = (const float*)d_in[10];
    float* out = (float*)d_out;

    cudaFuncSetAttribute(lstm2_kernel,
                         cudaFuncAttributeMaxDynamicSharedMemorySize, SMEM_BYTES);
    lstm2_kernel<<<NCTA, NTHR, SMEM_BYTES>>>(
        x, Wih0, Whh0, bih0, bhh0, Wih1, Whh1, bih1, bhh1, Wfc, bfc, out);
}

// round 11
// speedup vs baseline: 1.2722x; 1.2722x over previous
#include <cuda_runtime.h>

#define T_LEN  512
#define HH     50
#define G4     200
#define GB     16
#define NTHR   320     // 10 warps
#define NMV    250     // 5 slices * 25 gate-chunks * 2 batch-groups
#define NSL    5
#define NCTA   128
#define XCHUNK 64

// shared layout (float offsets, all 16B aligned)
#define OFF_W0T   0        // [50][200]   Whh0^T
#define OFF_WCT   10000    // [100][200]  [Wih1;Whh1]^T
#define OFF_WIH0  30000    // [200]
#define OFF_B0    30200    // [200]
#define OFF_B1    30400    // [200]
#define OFF_HCAT  30600    // [100][16]  rows 0..49 h1, 50..99 h2
#define OFF_C1    32200    // [50][16]
#define OFF_C2    33000    // [50][16]
#define OFF_PBUF  33800    // [5][200][16] partial gates
#define OFF_XS    49800    // [64][16] x chunk
#define SMEM_FLOATS 50824
#define SMEM_BYTES  (SMEM_FLOATS * 4)

typedef unsigned long long ull;

#define FFMA2(d, a, b) \
    asm("fma.rn.f32x2 %0, %1, %2, %0;" : "+l"(d) : "l"(a), "l"(b))
#define UNPACK2(lo, hi, v) \
    asm("mov.b64 {%0, %1}, %2;" : "=f"(lo), "=f"(hi) : "l"(v))
#define PACKDUP(d, s) \
    asm("mov.b64 %0, {%1, %1};" : "=l"(d) : "f"(s))

__device__ __forceinline__ float sigf(float x) {
    return __fdividef(1.f, 1.f + __expf(-x));
}
__device__ __forceinline__ float tanh_fast(float x) {
    return fmaf(2.f, __fdividef(1.f, 1.f + __expf(-2.f * x)), -1.f);
}

extern __shared__ float sm[];

__global__ __launch_bounds__(NTHR, 1)
void lstm2_kernel(const float* __restrict__ x,
                  const float* __restrict__ Wih0, const float* __restrict__ Whh0,
                  const float* __restrict__ bih0, const float* __restrict__ bhh0,
                  const float* __restrict__ Wih1, const float* __restrict__ Whh1,
                  const float* __restrict__ bih1, const float* __restrict__ bhh1,
                  const float* __restrict__ Wfc,  const float* __restrict__ bfc,
                  float* __restrict__ out)
{
    const int tid = threadIdx.x;
    const int b0  = blockIdx.x * GB;

    // ---- stage weights (transposed: gate index contiguous) ----
    for (int i = tid; i < G4 * HH; i += NTHR) {
        int j = i / HH, k = i % HH;
        sm[OFF_W0T + k * G4 + j]        = Whh0[i];
        sm[OFF_WCT + k * G4 + j]        = Wih1[i];
        sm[OFF_WCT + (HH + k) * G4 + j] = Whh1[i];
    }
    for (int i = tid; i < G4; i += NTHR) {
        sm[OFF_WIH0 + i] = Wih0[i];
        sm[OFF_B0 + i]   = bih0[i] + bhh0[i];
        sm[OFF_B1 + i]   = bih1[i] + bhh1[i];
    }
    for (int i = tid; i < 100 * GB; i += NTHR) sm[OFF_HCAT + i] = 0.f;
    for (int i = tid; i < HH * GB; i += NTHR) {
        sm[OFF_C1 + i] = 0.f;
        sm[OFF_C2 + i] = 0.f;
    }
    __syncthreads();

    const bool mv = (tid < NMV);
    const int  q  = tid / 50;          // k-slice 0..4
    const int  r  = tid % 50;
    const int  c  = r >> 1;            // gate chunk 0..24 (8 gates)
    const int  bg = r & 1;             // batch group 0..1 (8 batch)
    const int  gbase = 8 * c;
    const int  k0a = 10 * q, k0b = k0a + 10;     // layer0 k range
    const int  k1a = 20 * q, k1b = k1a + 20;     // layer1 k range

    // hoisted invariant gate-pairs
    ull w0p[4], b0p[4], b1p[4];
    if (mv) {
        #pragma unroll
        for (int p = 0; p < 4; ++p) {
            w0p[p] = *(const ull*)(sm + OFF_WIH0 + gbase + 2 * p);
            b0p[p] = *(const ull*)(sm + OFF_B0   + gbase + 2 * p);
            b1p[p] = *(const ull*)(sm + OFF_B1   + gbase + 2 * p);
        }
    }

    float* pbq = sm + OFF_PBUF + q * 3200;

    for (int t = 0; t < T_LEN; ++t) {
        // ---- stage next x chunk (every 64 steps) ----
        if ((t & (XCHUNK - 1)) == 0) {
            for (int i = tid; i < XCHUNK * GB; i += NTHR) {
                int b  = i / XCHUNK;
                int tt = i % XCHUNK;
                sm[OFF_XS + tt * GB + b] = x[(b0 + b) * T_LEN + t + tt];
            }
            __syncthreads();
        }

        // ================= layer 0 matvec (8g x 8b tile, k-split 5) =====
        if (mv) {
            ull acc[8][4];
            if (q == 0) {
                #pragma unroll
                for (int j = 0; j < 8; ++j) {
                    float xv = sm[OFF_XS + (t & (XCHUNK - 1)) * GB + 8 * bg + j];
                    ull xp; PACKDUP(xp, xv);
                    #pragma unroll
                    for (int p = 0; p < 4; ++p) {
                        acc[j][p] = b0p[p];
                        FFMA2(acc[j][p], w0p[p], xp);
                    }
                }
            } else {
                #pragma unroll
                for (int j = 0; j < 8; ++j)
                    #pragma unroll
                    for (int p = 0; p < 4; ++p) acc[j][p] = 0ull;
            }
            #pragma unroll 2
            for (int k = k0a; k < k0b; ++k) {
                const float* wrow = sm + OFF_W0T + k * G4 + gbase;
                ull wp[4];
                wp[0] = *(const ull*)(wrow);
                wp[1] = *(const ull*)(wrow + 2);
                wp[2] = *(const ull*)(wrow + 4);
                wp[3] = *(const ull*)(wrow + 6);
                const float* hrow = sm + OFF_HCAT + k * GB + 8 * bg;
                float4 hA = *(const float4*)(hrow);
                float4 hB = *(const float4*)(hrow + 4);
                ull hp[8];
                PACKDUP(hp[0], hA.x); PACKDUP(hp[1], hA.y);
                PACKDUP(hp[2], hA.z); PACKDUP(hp[3], hA.w);
                PACKDUP(hp[4], hB.x); PACKDUP(hp[5], hB.y);
                PACKDUP(hp[6], hB.z); PACKDUP(hp[7], hB.w);
                #pragma unroll
                for (int j = 0; j < 8; ++j)
                    #pragma unroll
                    for (int p = 0; p < 4; ++p)
                        FFMA2(acc[j][p], wp[p], hp[j]);
            }
            // store partials: pbuf[q][gate][batch]
            float v[8][8];
            #pragma unroll
            for (int j = 0; j < 8; ++j)
                #pragma unroll
                for (int p = 0; p < 4; ++p)
                    UNPACK2(v[2 * p][j], v[2 * p + 1][j], acc[j][p]);
            #pragma unroll
            for (int gi = 0; gi < 8; ++gi) {
                float* dst = pbq + (gbase + gi) * GB + 8 * bg;
                *(float4*)(dst)     = make_float4(v[gi][0], v[gi][1], v[gi][2], v[gi][3]);
                *(float4*)(dst + 4) = make_float4(v[gi][4], v[gi][5], v[gi][6], v[gi][7]);
            }
        }
        __syncthreads();

        // ================= layer 0 reduce + elementwise =================
        for (int i = tid; i < HH * GB; i += NTHR) {
            int k = i >> 4, b = i & 15;
            float gi = 0.f, gf = 0.f, gg = 0.f, go = 0.f;
            #pragma unroll
            for (int s = 0; s < NSL; ++s) {
                const float* pb = sm + OFF_PBUF + s * 3200;
                gi += pb[k * GB + b];
                gf += pb[(HH + k) * GB + b];
                gg += pb[(2 * HH + k) * GB + b];
                go += pb[(3 * HH + k) * GB + b];
            }
            gi = sigf(gi); gf = sigf(gf); gg = tanh_fast(gg); go = sigf(go);
            float cc = fmaf(gf, sm[OFF_C1 + k * GB + b], gi * gg);
            sm[OFF_C1 + k * GB + b]   = cc;
            sm[OFF_HCAT + k * GB + b] = go * tanh_fast(cc);
        }
        __syncthreads();

        // ================= layer 1 matvec (fused in+rec, K=100) =========
        if (mv) {
            ull acc[8][4];
            #pragma unroll
            for (int j = 0; j < 8; ++j)
                #pragma unroll
                for (int p = 0; p < 4; ++p)
                    acc[j][p] = (q == 0) ? b1p[p] : 0ull;
            #pragma unroll 2
            for (int k = k1a; k < k1b; ++k) {
                const float* wrow = sm + OFF_WCT + k * G4 + gbase;
                ull wp[4];
                wp[0] = *(const ull*)(wrow);
                wp[1] = *(const ull*)(wrow + 2);
                wp[2] = *(const ull*)(wrow + 4);
                wp[3] = *(const ull*)(wrow + 6);
                const float* hrow = sm + OFF_HCAT + k * GB + 8 * bg;
                float4 hA = *(const float4*)(hrow);
                float4 hB = *(const float4*)(hrow + 4);
                ull hp[8];
                PACKDUP(hp[0], hA.x); PACKDUP(hp[1], hA.y);
                PACKDUP(hp[2], hA.z); PACKDUP(hp[3], hA.w);
                PACKDUP(hp[4], hB.x); PACKDUP(hp[5], hB.y);
                PACKDUP(hp[6], hB.z); PACKDUP(hp[7], hB.w);
                #pragma unroll
                for (int j = 0; j < 8; ++j)
                    #pragma unroll
                    for (int p = 0; p < 4; ++p)
                        FFMA2(acc[j][p], wp[p], hp[j]);
            }
            float v[8][8];
            #pragma unroll
            for (int j = 0; j < 8; ++j)
                #pragma unroll
                for (int p = 0; p < 4; ++p)
                    UNPACK2(v[2 * p][j], v[2 * p + 1][j], acc[j][p]);
            #pragma unroll
            for (int gi = 0; gi < 8; ++gi) {
                float* dst = pbq + (gbase + gi) * GB + 8 * bg;
                *(float4*)(dst)     = make_float4(v[gi][0], v[gi][1], v[gi][2], v[gi][3]);
                *(float4*)(dst + 4) = make_float4(v[gi][4], v[gi][5], v[gi][6], v[gi][7]);
            }
        }
        __syncthreads();

        // ================= layer 1 reduce + elementwise =================
        for (int i = tid; i < HH * GB; i += NTHR) {
            int k = i >> 4, b = i & 15;
            float gi = 0.f, gf = 0.f, gg = 0.f, go = 0.f;
            #pragma unroll
            for (int s = 0; s < NSL; ++s) {
                const float* pb = sm + OFF_PBUF + s * 3200;
                gi += pb[k * GB + b];
                gf += pb[(HH + k) * GB + b];
                gg += pb[(2 * HH + k) * GB + b];
                go += pb[(3 * HH + k) * GB + b];
            }
            gi = sigf(gi); gf = sigf(gf); gg = tanh_fast(gg); go = sigf(go);
            float cc = fmaf(gf, sm[OFF_C2 + k * GB + b], gi * gg);
            sm[OFF_C2 + k * GB + b]          = cc;
            sm[OFF_HCAT + (HH + k) * GB + b] = go * tanh_fast(cc);
        }
        __syncthreads();
    }

    // ================= final classifier on h2[T-1] =================
    if (tid < GB * 2) {
        int bb = tid >> 1, cls = tid & 1;
        float acc = bfc[cls];
        #pragma unroll
        for (int k = 0; k < HH; ++k)
            acc = fmaf(Wfc[cls * HH + k], sm[OFF_HCAT + (HH + k) * GB + bb], acc);
        out[(b0 + bb) * 2 + cls] = acc;
    }
}

extern "C" void kernel_launch(void* const* d_in, const int* in_sizes, int n_in,
                              void* d_out, int out_size)
{
    const float* x    = (const float*)d_in[0];
    const float* Wih0 = (const float*)d_in[1];
    const float* Whh0 = (const float*)d_in[2];
    const float* bih0 = (const float*)d_in[3];
    const float* bhh0 = (const float*)d_in[4];
    const float* Wih1 = (const float*)d_in[5];
    const float* Whh1 = (const float*)d_in[6];
    const float* bih1 = (const float*)d_in[7];
    const float* bhh1 = (const float*)d_in[8];
    const float* Wfc  = (const float*)d_in[9];
    const float* bfc  = (const float*)d_in[10];
    float* out = (float*)d_out;

    cudaFuncSetAttribute(lstm2_kernel,
                         cudaFuncAttributeMaxDynamicSharedMemorySize, SMEM_BYTES);
    lstm2_kernel<<<NCTA, NTHR, SMEM_BYTES>>>(
        x, Wih0, Whh0, bih0, bhh0, Wih1, Whh1, bih1, bhh1, Wfc, bfc, out);
}

// round 12
// speedup vs baseline: 1.7737x; 1.3941x over previous
#include <cuda_runtime.h>

#define T_LEN  512
#define HH     50
#define G4     200
#define GB     16
#define NTHR   320
#define NCTA   128
#define XCHUNK 64
#define HS     20      // hcat row stride (pad -> bank spread on h stores)

// shared layout (float offsets)
#define OFF_W0T   0        // [50][200]   Whh0^T
#define OFF_WCT   10000    // [100][200]  [Wih1;Whh1]^T
#define OFF_WIH0  30000    // [200]
#define OFF_B0    30200    // [200]
#define OFF_B1    30400    // [200]
#define OFF_HCAT  30600    // [100][20]  rows 0..49 h1(t-1), 50..99 h2(t-2)
#define OFF_XS    32600    // [64][16]
#define SMEM_FLOATS 33624
#define SMEM_BYTES  (SMEM_FLOATS * 4)

typedef unsigned long long ull;

#define FFMA2(d, a, b) asm("fma.rn.f32x2 %0, %1, %2, %0;" : "+l"(d) : "l"(a), "l"(b))
#define ADDF2(d, a)    asm("add.rn.f32x2 %0, %0, %1;" : "+l"(d) : "l"(a))
#define UNPACK2(lo, hi, v) asm("mov.b64 {%0, %1}, %2;" : "=f"(lo), "=f"(hi) : "l"(v))
#define PACKDUP(d, s)  asm("mov.b64 %0, {%1, %1};" : "=l"(d) : "f"(s))

__device__ __forceinline__ ull shfl_xor_u64(ull v, int m) {
    unsigned lo, hi;
    asm("mov.b64 {%0, %1}, %2;" : "=r"(lo), "=r"(hi) : "l"(v));
    lo = __shfl_xor_sync(0xffffffffu, lo, m);
    hi = __shfl_xor_sync(0xffffffffu, hi, m);
    ull r;
    asm("mov.b64 %0, {%1, %2};" : "=l"(r) : "r"(lo), "r"(hi));
    return r;
}

__device__ __forceinline__ float sigf(float x) {
    return __fdividef(1.f, 1.f + __expf(-x));
}
__device__ __forceinline__ float tanh_fast(float x) {
    return fmaf(2.f, __fdividef(1.f, 1.f + __expf(-2.f * x)), -1.f);
}

extern __shared__ float sm[];

__global__ __launch_bounds__(NTHR, 1)
void lstm2_kernel(const float* __restrict__ x,
                  const float* __restrict__ Wih0, const float* __restrict__ Whh0,
                  const float* __restrict__ bih0, const float* __restrict__ bhh0,
                  const float* __restrict__ Wih1, const float* __restrict__ Whh1,
                  const float* __restrict__ bih1, const float* __restrict__ bhh1,
                  const float* __restrict__ Wfc,  const float* __restrict__ bfc,
                  float* __restrict__ out)
{
    const int tid = threadIdx.x;
    const int b0  = blockIdx.x * GB;

    // ---- stage weights (transposed: gate index contiguous) ----
    for (int i = tid; i < G4 * HH; i += NTHR) {
        int j = i / HH, k = i % HH;
        sm[OFF_W0T + k * G4 + j]        = Whh0[i];
        sm[OFF_WCT + k * G4 + j]        = Wih1[i];
        sm[OFF_WCT + (HH + k) * G4 + j] = Whh1[i];
    }
    for (int i = tid; i < G4; i += NTHR) {
        sm[OFF_WIH0 + i] = Wih0[i];
        sm[OFF_B0 + i]   = bih0[i] + bhh0[i];
        sm[OFF_B1 + i]   = bih1[i] + bhh1[i];
    }
    for (int i = tid; i < 100 * HS; i += NTHR) sm[OFF_HCAT + i] = 0.f;
    __syncthreads();

    // thread roles: tid 0..99 -> layer0 (2 k-slices), 100..299 -> layer1 (4 k-slices)
    const bool isMV = (tid < 300);
    const bool isL1 = (tid >= 100);
    const int  u    = isL1 ? (tid - 100) : tid;
    const int  q    = isL1 ? (u & 3) : (u & 1);
    const int  cb   = isL1 ? (u >> 2) : (u >> 1);
    const int  c    = cb % 25;            // unit chunk: units 2c, 2c+1
    const int  bg   = cb / 25;            // batch group (8 rows); junk threads: bg=2
    const int  kstart = 25 * q;
    // XOR batch permutation: slot r holds physical batch (r ^ xm)
    const int  xm  = isL1 ? ((2 * q) & 6) : (4 * q);
    const int  dA  = isL1 ? 2 : 1;        // round-A shuffle distance

    const float* wb = sm + (isL1 ? OFF_WCT : OFF_W0T) + kstart * G4 + 2 * c;
    const float* hb = sm + OFF_HCAT + kstart * HS + 8 * bg;
    const float* hbp0 = hb + (0 ^ xm);
    const float* hbp1 = hb + (2 ^ xm);
    const float* hbp2 = hb + (4 ^ xm);
    const float* hbp3 = hb + (6 ^ xm);

    const bool addBias = (q == 0);
    const bool addX    = (!isL1) && (q == 0);

    // invariant gate-pairs (units 2c,2c+1 of each gate type p)
    ull bp[4], w0p[4];
    {
        const float* bs = sm + (isL1 ? OFF_B1 : OFF_B0) + 2 * c;
        const float* ws = sm + OFF_WIH0 + 2 * c;
        #pragma unroll
        for (int p = 0; p < 4; ++p) {
            bp[p]  = *(const ull*)(bs + 50 * p);
            w0p[p] = *(const ull*)(ws + 50 * p);
        }
    }

    // cell state in registers: cst[m] unit 2c, cst[4+m] unit 2c+1
    float cst[8];
    #pragma unroll
    for (int i = 0; i < 8; ++i) cst[i] = 0.f;

    const int hrow0 = (isL1 ? (HH + 2 * c) : (2 * c)) * HS;
    const int hrow1 = hrow0 + HS;
    const int boff  = 8 * bg + xm;        // batch base this lane owns after reduce

    for (int t = 0; t <= T_LEN; ++t) {
        // ---- stage x chunk ----
        if ((t & (XCHUNK - 1)) == 0 && t < T_LEN) {
            for (int i = tid; i < XCHUNK * GB; i += NTHR) {
                int b = i / XCHUNK, tt = i % XCHUNK;
                sm[OFF_XS + tt * GB + b] = x[(b0 + b) * T_LEN + t + tt];
            }
            __syncthreads();
        }

        // ================= fused matvec: gates0(t) + gates1(t-1) =========
        ull acc[8][4];
        #pragma unroll
        for (int j = 0; j < 8; ++j)
            #pragma unroll
            for (int p = 0; p < 4; ++p)
                acc[j][p] = addBias ? bp[p] : 0ull;

        if (addX) {
            const float* xr = sm + OFF_XS + (t & (XCHUNK - 1)) * GB + 8 * bg;
            #pragma unroll
            for (int j = 0; j < 8; ++j) {
                ull xp; PACKDUP(xp, xr[j ^ xm]);
                #pragma unroll
                for (int p = 0; p < 4; ++p) FFMA2(acc[j][p], w0p[p], xp);
            }
        }

        #pragma unroll 5
        for (int k = 0; k < 25; ++k) {
            const float* wr = wb + k * G4;
            ull wp0 = *(const ull*)(wr);
            ull wp1 = *(const ull*)(wr + 50);
            ull wp2 = *(const ull*)(wr + 100);
            ull wp3 = *(const ull*)(wr + 150);
            float2 v0 = *(const float2*)(hbp0 + k * HS);
            float2 v1 = *(const float2*)(hbp1 + k * HS);
            float2 v2 = *(const float2*)(hbp2 + k * HS);
            float2 v3 = *(const float2*)(hbp3 + k * HS);
            ull hp[8];
            PACKDUP(hp[0], v0.x); PACKDUP(hp[1], v0.y);
            PACKDUP(hp[2], v1.x); PACKDUP(hp[3], v1.y);
            PACKDUP(hp[4], v2.x); PACKDUP(hp[5], v2.y);
            PACKDUP(hp[6], v3.x); PACKDUP(hp[7], v3.y);
            #pragma unroll
            for (int j = 0; j < 8; ++j) {
                FFMA2(acc[j][0], wp0, hp[j]);
                FFMA2(acc[j][1], wp1, hp[j]);
                FFMA2(acc[j][2], wp2, hp[j]);
                FFMA2(acc[j][3], wp3, hp[j]);
            }
        }

        // ============ in-warp k-reduction (XOR-permuted reduce-scatter) ==
        // round A: fold slots 4..7 into 0..3 (L0 done after this)
        #pragma unroll
        for (int m = 0; m < 4; ++m)
            #pragma unroll
            for (int p = 0; p < 4; ++p) {
                ull o = shfl_xor_u64(acc[m + 4][p], dA);
                ADDF2(acc[m][p], o);
            }
        // round B: fold slots 2..3 into 0..1 (L1 only; shfl executed by all)
        #pragma unroll
        for (int m = 0; m < 2; ++m)
            #pragma unroll
            for (int p = 0; p < 4; ++p) {
                ull o = shfl_xor_u64(acc[m + 2][p], 1);
                if (isL1) ADDF2(acc[m][p], o);
            }

        // ================= elementwise (registers only) =================
        const bool doUpd = isMV && (isL1 ? (t > 0) : (t < T_LEN));
        float h0v[4], h1v[4];
        if (doUpd) {
            #pragma unroll
            for (int m = 0; m < 4; ++m) {
                if (!isL1 || m < 2) {
                    float gi0, gi1, gf0, gf1, gg0, gg1, go0, go1;
                    UNPACK2(gi0, gi1, acc[m][0]);
                    UNPACK2(gf0, gf1, acc[m][1]);
                    UNPACK2(gg0, gg1, acc[m][2]);
                    UNPACK2(go0, go1, acc[m][3]);
                    float c0 = fmaf(sigf(gf0), cst[m],     sigf(gi0) * tanh_fast(gg0));
                    float c1 = fmaf(sigf(gf1), cst[4 + m], sigf(gi1) * tanh_fast(gg1));
                    cst[m] = c0; cst[4 + m] = c1;
                    h0v[m] = sigf(go0) * tanh_fast(c0);
                    h1v[m] = sigf(go1) * tanh_fast(c1);
                }
            }
        }
        __syncthreads();   // all matvec h-reads done before h writes
        if (doUpd) {
            float* hd0 = sm + OFF_HCAT + hrow0 + boff;
            float* hd1 = sm + OFF_HCAT + hrow1 + boff;
            if (isL1) {
                *(float2*)hd0 = make_float2(h0v[0], h0v[1]);
                *(float2*)hd1 = make_float2(h1v[0], h1v[1]);
            } else {
                *(float4*)hd0 = make_float4(h0v[0], h0v[1], h0v[2], h0v[3]);
                *(float4*)hd1 = make_float4(h1v[0], h1v[1], h1v[2], h1v[3]);
            }
        }
        __syncthreads();
    }

    // ================= final classifier on h2[T-1] =================
    if (tid < GB * 2) {
        int bb = tid >> 1, cls = tid & 1;
        float acc = bfc[cls];
        #pragma unroll
        for (int k = 0; k < HH; ++k)
            acc = fmaf(Wfc[cls * HH + k], sm[OFF_HCAT + (HH + k) * HS + bb], acc);
        out[(b0 + bb) * 2 + cls] = acc;
    }
}

extern "C" void kernel_launch(void* const* d_in, const int* in_sizes, int n_in,
                              void* d_out, int out_size)
{
    const float* x    = (const float*)d_in[0];
    const float* Wih0 = (const float*)d_in[1];
    const float* Whh0 = (const float*)d_in[2];
    const float* bih0 = (const float*)d_in[3];
    const float* bhh0 = (const float*)d_in[4];
    const float* Wih1 = (const float*)d_in[5];
    const float* Whh1 = (const float*)d_in[6];
    const float* bih1 = (const float*)d_in[7];
    const float* bhh1 = (const float*)d_in[8];
    const float* Wfc  = (const float*)d_in[9];
    const float* bfc  = (const float*)d_in[10];
    float* out = (float*)d_out;

    cudaFuncSetAttribute(lstm2_kernel,
                         cudaFuncAttributeMaxDynamicSharedMemorySize, SMEM_BYTES);
    lstm2_kernel<<<NCTA, NTHR, SMEM_BYTES>>>(
        x, Wih0, Whh0, bih0, bhh0, Wih1, Whh1, bih1, bhh1, Wfc, bfc, out);
}

// round 13
// speedup vs baseline: 1.7790x; 1.0030x over previous
#include <cuda_runtime.h>

#define T_LEN  512
#define HH     50
#define G4     200
#define GB     16
#define NTHR   320
#define NCTA   128
#define XCHUNK 64
#define HS     20
#define HBUF   (100 * HS)   // 2000 floats per h buffer

// shared layout (float offsets)
#define OFF_W0T   0        // [50][200]  relayout: k*200 + c*8 + p*2 + e
#define OFF_WCT   10000    // [100][200] same (rows 0..49 h1-dims, 50..99 h2-dims)
#define OFF_WIH0  30000    // [200] original gate order
#define OFF_B0    30200
#define OFF_B1    30400
#define OFF_HCAT  30600    // [2][100][20] double-buffered
#define OFF_XS    34600    // [64][16]
#define SMEM_FLOATS 35624
#define SMEM_BYTES  (SMEM_FLOATS * 4)

typedef unsigned long long ull;

#define FFMA2(d, a, b) asm("fma.rn.f32x2 %0, %1, %2, %0;" : "+l"(d) : "l"(a), "l"(b))
#define ADDF2(d, a)    asm("add.rn.f32x2 %0, %0, %1;" : "+l"(d) : "l"(a))
#define UNPACK2(lo, hi, v) asm("mov.b64 {%0, %1}, %2;" : "=f"(lo), "=f"(hi) : "l"(v))
#define PACKDUP(d, s)  asm("mov.b64 %0, {%1, %1};" : "=l"(d) : "f"(s))

__device__ __forceinline__ ull shfl_xor_u64(ull v, int m) {
    unsigned lo, hi;
    asm("mov.b64 {%0, %1}, %2;" : "=r"(lo), "=r"(hi) : "l"(v));
    lo = __shfl_xor_sync(0xffffffffu, lo, m);
    hi = __shfl_xor_sync(0xffffffffu, hi, m);
    ull r;
    asm("mov.b64 %0, {%1, %2};" : "=l"(r) : "r"(lo), "r"(hi));
    return r;
}

__device__ __forceinline__ float sigf(float x) {
    return __fdividef(1.f, 1.f + __expf(-x));
}
__device__ __forceinline__ float tanh_fast(float x) {
    return fmaf(2.f, __fdividef(1.f, 1.f + __expf(-2.f * x)), -1.f);
}

extern __shared__ float sm[];

__global__ __launch_bounds__(NTHR, 1)
void lstm2_kernel(const float* __restrict__ x,
                  const float* __restrict__ Wih0, const float* __restrict__ Whh0,
                  const float* __restrict__ bih0, const float* __restrict__ bhh0,
                  const float* __restrict__ Wih1, const float* __restrict__ Whh1,
                  const float* __restrict__ bih1, const float* __restrict__ bhh1,
                  const float* __restrict__ Wfc,  const float* __restrict__ bfc,
                  float* __restrict__ out)
{
    const int tid = threadIdx.x;
    const int b0  = blockIdx.x * GB;

    // ---- stage weights: relayout [k][c][p*2+e] (thread's 32B contiguous) ----
    for (int i = tid; i < G4 * HH; i += NTHR) {
        int j = i / HH, k = i % HH;           // j: gate 0..199, k: 0..49
        int p = j / 50, rm = j % 50, cc = rm >> 1, e = rm & 1;
        int dst = k * G4 + cc * 8 + p * 2 + e;
        sm[OFF_W0T + dst]            = Whh0[i];
        sm[OFF_WCT + dst]            = Wih1[i];
        sm[OFF_WCT + 50 * G4 + dst]  = Whh1[i];
    }
    for (int i = tid; i < G4; i += NTHR) {
        sm[OFF_WIH0 + i] = Wih0[i];
        sm[OFF_B0 + i]   = bih0[i] + bhh0[i];
        sm[OFF_B1 + i]   = bih1[i] + bhh1[i];
    }
    for (int i = tid; i < 2 * HBUF; i += NTHR) sm[OFF_HCAT + i] = 0.f;
    __syncthreads();

    // roles: tid 0..199 -> L1 (4 k-slices), 200..299 -> L0 (2 k-slices)
    // lane-aligned: bg in bit0, q in bits 1.. so shfl-XOR partners stay in-warp
    const bool isL1 = (tid < 200);
    const bool isMV = (tid < 300);
    const int  u    = isL1 ? tid : (tid - 200);
    const int  bg   = u & 1;
    const int  q    = isL1 ? ((u >> 1) & 3) : ((u >> 1) & 1);
    const int  craw = isL1 ? (u >> 3) : (u >> 2);
    const int  c    = craw < 25 ? craw : 24;            // clamp for junk lanes
    const int  kstart = 25 * q;
    const int  xm  = isL1 ? ((2 * q) & 6) : (4 * q);
    const int  rdA = isL1 ? 4 : 2;                      // lane XOR distance, round A

    const float* wb = sm + (isL1 ? OFF_WCT : OFF_W0T) + kstart * G4 + 8 * c;
    const int hoff  = kstart * HS + 8 * bg;
    const int ho0 = hoff + (0 ^ xm), ho1 = hoff + (2 ^ xm);
    const int ho2 = hoff + (4 ^ xm), ho3 = hoff + (6 ^ xm);

    const bool addBias = (q == 0);
    const bool addX    = (!isL1) && (q == 0);

    // invariant gate-pairs (units 2c,2c+1 per gate type p; original layout)
    ull bp[4], w0p[4];
    {
        const float* bs = sm + (isL1 ? OFF_B1 : OFF_B0) + 2 * c;
        const float* ws = sm + OFF_WIH0 + 2 * c;
        #pragma unroll
        for (int p = 0; p < 4; ++p) {
            bp[p]  = *(const ull*)(bs + 50 * p);
            w0p[p] = *(const ull*)(ws + 50 * p);
        }
    }

    float cst[8];
    #pragma unroll
    for (int i = 0; i < 8; ++i) cst[i] = 0.f;

    const int hrow0 = (isL1 ? (HH + 2 * c) : (2 * c)) * HS;
    const int hrow1 = hrow0 + HS;
    const int boff  = 8 * bg + xm;

    for (int t = 0; t <= T_LEN; ++t) {
        if ((t & (XCHUNK - 1)) == 0 && t < T_LEN) {
            for (int i = tid; i < XCHUNK * GB; i += NTHR) {
                int b = i / XCHUNK, tt = i % XCHUNK;
                sm[OFF_XS + tt * GB + b] = x[(b0 + b) * T_LEN + t + tt];
            }
            __syncthreads();
        }

        const float* hc = sm + OFF_HCAT + (t & 1) * HBUF;       // read buffer

        // ================= fused matvec: gates0(t) + gates1(t-1) =========
        ull acc[8][4];
        #pragma unroll
        for (int j = 0; j < 8; ++j)
            #pragma unroll
            for (int p = 0; p < 4; ++p)
                acc[j][p] = addBias ? bp[p] : 0ull;

        if (addX) {
            const float* xr = sm + OFF_XS + (t & (XCHUNK - 1)) * GB + 8 * bg;
            #pragma unroll
            for (int j = 0; j < 8; ++j) {
                ull xp; PACKDUP(xp, xr[j]);   // xm==0 when addX
                #pragma unroll
                for (int p = 0; p < 4; ++p) FFMA2(acc[j][p], w0p[p], xp);
            }
        }

        #pragma unroll 5
        for (int k = 0; k < 25; ++k) {
            const float* wr = wb + k * G4;
            ulonglong2 wA = *(const ulonglong2*)(wr);       // pairs p=0,1
            ulonglong2 wB = *(const ulonglong2*)(wr + 4);   // pairs p=2,3
            float2 v0 = *(const float2*)(hc + ho0 + k * HS);
            float2 v1 = *(const float2*)(hc + ho1 + k * HS);
            float2 v2 = *(const float2*)(hc + ho2 + k * HS);
            float2 v3 = *(const float2*)(hc + ho3 + k * HS);
            ull hp[8];
            PACKDUP(hp[0], v0.x); PACKDUP(hp[1], v0.y);
            PACKDUP(hp[2], v1.x); PACKDUP(hp[3], v1.y);
            PACKDUP(hp[4], v2.x); PACKDUP(hp[5], v2.y);
            PACKDUP(hp[6], v3.x); PACKDUP(hp[7], v3.y);
            #pragma unroll
            for (int j = 0; j < 8; ++j) {
                FFMA2(acc[j][0], wA.x, hp[j]);
                FFMA2(acc[j][1], wA.y, hp[j]);
                FFMA2(acc[j][2], wB.x, hp[j]);
                FFMA2(acc[j][3], wB.y, hp[j]);
            }
        }

        // ============ in-warp k-reduction (XOR-permuted reduce-scatter) ==
        #pragma unroll
        for (int m = 0; m < 4; ++m)
            #pragma unroll
            for (int p = 0; p < 4; ++p) {
                ull o = shfl_xor_u64(acc[m + 4][p], rdA);
                ADDF2(acc[m][p], o);
            }
        #pragma unroll
        for (int m = 0; m < 2; ++m)
            #pragma unroll
            for (int p = 0; p < 4; ++p) {
                ull o = shfl_xor_u64(acc[m + 2][p], 2);
                if (isL1) ADDF2(acc[m][p], o);
            }

        // ================= elementwise (registers only) =================
        const bool doUpd = isMV && (isL1 ? (t > 0) : (t < T_LEN));
        float h0v[4], h1v[4];
        if (doUpd) {
            #pragma unroll
            for (int m = 0; m < 4; ++m) {
                if (!isL1 || m < 2) {
                    float gi0, gi1, gf0, gf1, gg0, gg1, go0, go1;
                    UNPACK2(gi0, gi1, acc[m][0]);
                    UNPACK2(gf0, gf1, acc[m][1]);
                    UNPACK2(gg0, gg1, acc[m][2]);
                    UNPACK2(go0, go1, acc[m][3]);
                    float c0 = fmaf(sigf(gf0), cst[m],     sigf(gi0) * tanh_fast(gg0));
                    float c1 = fmaf(sigf(gf1), cst[4 + m], sigf(gi1) * tanh_fast(gg1));
                    cst[m] = c0; cst[4 + m] = c1;
                    h0v[m] = sigf(go0) * tanh_fast(c0);
                    h1v[m] = sigf(go1) * tanh_fast(c1);
                }
            }
            float* hw = sm + OFF_HCAT + ((t + 1) & 1) * HBUF;   // write buffer
            float* hd0 = hw + hrow0 + boff;
            float* hd1 = hw + hrow1 + boff;
            if (isL1) {
                *(float2*)hd0 = make_float2(h0v[0], h0v[1]);
                *(float2*)hd1 = make_float2(h1v[0], h1v[1]);
            } else {
                *(float4*)hd0 = make_float4(h0v[0], h0v[1], h0v[2], h0v[3]);
                *(float4*)hd1 = make_float4(h1v[0], h1v[1], h1v[2], h1v[3]);
            }
        }
        __syncthreads();   // single barrier: writes(buf wp) visible; reads(buf rp) done
    }

    // ================= final classifier on h2[T-1] =================
    // last L1 write was at t=T_LEN into buf[(T_LEN+1)&1]
    const float* hf = sm + OFF_HCAT + ((T_LEN + 1) & 1) * HBUF;
    if (tid < GB * 2) {
        int bb = tid >> 1, cls = tid & 1;
        float acc = bfc[cls];
        #pragma unroll
        for (int k = 0; k < HH; ++k)
            acc = fmaf(Wfc[cls * HH + k], hf[(HH + k) * HS + bb], acc);
        out[(b0 + bb) * 2 + cls] = acc;
    }
}

extern "C" void kernel_launch(void* const* d_in, const int* in_sizes, int n_in,
                              void* d_out, int out_size)
{
    const float* x    = (const float*)d_in[0];
    const float* Wih0 = (const float*)d_in[1];
    const float* Whh0 = (const float*)d_in[2];
    const float* bih0 = (const float*)d_in[3];
    const float* bhh0 = (const float*)d_in[4];
    const float* Wih1 = (const float*)d_in[5];
    const float* Whh1 = (const float*)d_in[6];
    const float* bih1 = (const float*)d_in[7];
    const float* bhh1 = (const float*)d_in[8];
    const float* Wfc  = (const float*)d_in[9];
    const float* bfc  = (const float*)d_in[10];
    float* out = (float*)d_out;

    cudaFuncSetAttribute(lstm2_kernel,
                         cudaFuncAttributeMaxDynamicSharedMemorySize, SMEM_BYTES);
    lstm2_kernel<<<NCTA, NTHR, SMEM_BYTES>>>(
        x, Wih0, Whh0, bih0, bhh0, Wih1, Whh1, bih1, bhh1, Wfc, bfc, out);
}

// round 15
// speedup vs baseline: 1.8801x; 1.0568x over previous
#include <cuda_runtime.h>

#define T_LEN  512
#define HH     50
#define G4     200
#define GB     16
#define NTHR   608     // 19 warps; 600 active
#define NCTA   128
#define XCHUNK 64
#define HS     20
#define HBUF   (100 * HS)

// shared layout (float offsets)
#define OFF_W0T   0        // [50][200]  relayout: k*200 + c*8 + p*2 + e
#define OFF_WCT   10000    // [100][200] same
#define OFF_WIH0  30000    // [200] original gate order
#define OFF_B0    30200
#define OFF_B1    30400
#define OFF_HCAT  30600    // [2][100][20] double-buffered
#define OFF_XS    34600    // [64][16]
#define SMEM_FLOATS 35624
#define SMEM_BYTES  (SMEM_FLOATS * 4)

typedef unsigned long long ull;

#define FFMA2(d, a, b) asm("fma.rn.f32x2 %0, %1, %2, %0;" : "+l"(d) : "l"(a), "l"(b))
#define ADDF2(d, a)    asm("add.rn.f32x2 %0, %0, %1;" : "+l"(d) : "l"(a))
#define UNPACK2(lo, hi, v) asm("mov.b64 {%0, %1}, %2;" : "=f"(lo), "=f"(hi) : "l"(v))
#define PACKDUP(d, s)  asm("mov.b64 %0, {%1, %1};" : "=l"(d) : "f"(s))

__device__ __forceinline__ ull shfl_xor_u64(ull v, int m) {
    unsigned lo, hi;
    asm("mov.b64 {%0, %1}, %2;" : "=r"(lo), "=r"(hi) : "l"(v));
    lo = __shfl_xor_sync(0xffffffffu, lo, m);
    hi = __shfl_xor_sync(0xffffffffu, hi, m);
    ull r;
    asm("mov.b64 %0, {%1, %2};" : "=l"(r) : "r"(lo), "r"(hi));
    return r;
}

__device__ __forceinline__ float sigf(float x) {
    return __fdividef(1.f, 1.f + __expf(-x));
}
__device__ __forceinline__ float tanh_fast(float x) {
    return fmaf(2.f, __fdividef(1.f, 1.f + __expf(-2.f * x)), -1.f);
}

extern __shared__ float sm[];

__global__ __launch_bounds__(NTHR, 1)
void lstm2_kernel(const float* __restrict__ x,
                  const float* __restrict__ Wih0, const float* __restrict__ Whh0,
                  const float* __restrict__ bih0, const float* __restrict__ bhh0,
                  const float* __restrict__ Wih1, const float* __restrict__ Whh1,
                  const float* __restrict__ bih1, const float* __restrict__ bhh1,
                  const float* __restrict__ Wfc,  const float* __restrict__ bfc,
                  float* __restrict__ out)
{
    const int tid = threadIdx.x;
    const int b0  = blockIdx.x * GB;

    // ---- stage weights: relayout [k][c][p*2+e] ----
    for (int i = tid; i < G4 * HH; i += NTHR) {
        int j = i / HH, k = i % HH;
        int p = j / 50, rm = j % 50, cc = rm >> 1, e = rm & 1;
        int dst = k * G4 + cc * 8 + p * 2 + e;
        sm[OFF_W0T + dst]            = Whh0[i];
        sm[OFF_WCT + dst]            = Wih1[i];
        sm[OFF_WCT + 50 * G4 + dst]  = Whh1[i];
    }
    for (int i = tid; i < G4; i += NTHR) {
        sm[OFF_WIH0 + i] = Wih0[i];
        sm[OFF_B0 + i]   = bih0[i] + bhh0[i];
        sm[OFF_B1 + i]   = bih1[i] + bhh1[i];
    }
    for (int i = tid; i < 2 * HBUF; i += NTHR) sm[OFF_HCAT + i] = 0.f;
    __syncthreads();

    // roles: tid 0..399 -> L1 (4 k-slices x 25 chunks x 4 bg)
    //        tid 400..599 -> L0 (2 k-slices x 25 chunks x 4 bg)
    const bool isL1 = (tid < 400);
    const bool isL0 = (tid >= 400) && (tid < 600);
    const int  u    = isL1 ? tid : (tid - 400);
    const int  bg   = u & 3;                       // batch group (4 rows)
    const int  q    = isL1 ? ((u >> 2) & 3) : ((u >> 2) & 1);
    const int  craw = isL1 ? (u >> 4) : (u >> 3);
    const int  c    = craw < 25 ? craw : 24;       // units 2c, 2c+1
    const int  kstart = 25 * q;
    const int  xme  = isL1 ? (q & ~1) : (2 * q);   // even effective permutation
    const bool eswap = isL1 && (q & 1);
    const int  rdA  = isL1 ? 8 : 4;

    const float* wb = sm + (isL1 ? OFF_WCT : OFF_W0T) + kstart * G4 + 8 * c;
    const int hoA = kstart * HS + 4 * bg + xme;         // slots 0,1
    const int hoB = kstart * HS + 4 * bg + (2 ^ xme);   // slots 2,3

    const bool addBias = (q == 0);
    const bool addX    = isL0 && (q == 0);

    // invariant gate-pairs (units 2c,2c+1 per gate type p; original layout)
    ull bp[4], w0p[4];
    {
        const float* bs = sm + (isL1 ? OFF_B1 : OFF_B0) + 2 * c;
        const float* ws = sm + OFF_WIH0 + 2 * c;
        #pragma unroll
        for (int p = 0; p < 4; ++p) {
            bp[p]  = *(const ull*)(bs + 50 * p);
            w0p[p] = *(const ull*)(ws + 50 * p);
        }
    }

    float cst[4];
    #pragma unroll
    for (int i = 0; i < 4; ++i) cst[i] = 0.f;

    const int hrow0 = (isL1 ? (HH + 2 * c) : (2 * c)) * HS;
    const int hrow1 = hrow0 + HS;

    for (int t = 0; t <= T_LEN; ++t) {
        if ((t & (XCHUNK - 1)) == 0 && t < T_LEN) {
            for (int i = tid; i < XCHUNK * GB; i += NTHR) {
                int b = i / XCHUNK, tt = i % XCHUNK;
                sm[OFF_XS + tt * GB + b] = x[(b0 + b) * T_LEN + t + tt];
            }
            __syncthreads();
        }

        const float* hc = sm + OFF_HCAT + (t & 1) * HBUF;   // read buffer

        // ================= fused matvec: gates0(t) + gates1(t-1) =========
        ull acc[4][4];
        #pragma unroll
        for (int j = 0; j < 4; ++j)
            #pragma unroll
            for (int p = 0; p < 4; ++p)
                acc[j][p] = addBias ? bp[p] : 0ull;

        if (addX) {   // L0, q==0: slot labels are identity
            const float* xr = sm + OFF_XS + (t & (XCHUNK - 1)) * GB + 4 * bg;
            #pragma unroll
            for (int j = 0; j < 4; ++j) {
                ull xp; PACKDUP(xp, xr[j]);
                #pragma unroll
                for (int p = 0; p < 4; ++p) FFMA2(acc[j][p], w0p[p], xp);
            }
        }

        #pragma unroll 5
        for (int k = 0; k < 25; ++k) {
            const float* wr = wb + k * G4;
            ulonglong2 wA = *(const ulonglong2*)(wr);       // gate pairs p=0,1
            ulonglong2 wB = *(const ulonglong2*)(wr + 4);   // gate pairs p=2,3
            float2 vA = *(const float2*)(hc + hoA + k * HS);
            float2 vB = *(const float2*)(hc + hoB + k * HS);
            ull hp0, hp1, hp2, hp3;
            PACKDUP(hp0, vA.x); PACKDUP(hp1, vA.y);
            PACKDUP(hp2, vB.x); PACKDUP(hp3, vB.y);
            FFMA2(acc[0][0], wA.x, hp0); FFMA2(acc[0][1], wA.y, hp0);
            FFMA2(acc[0][2], wB.x, hp0); FFMA2(acc[0][3], wB.y, hp0);
            FFMA2(acc[1][0], wA.x, hp1); FFMA2(acc[1][1], wA.y, hp1);
            FFMA2(acc[1][2], wB.x, hp1); FFMA2(acc[1][3], wB.y, hp1);
            FFMA2(acc[2][0], wA.x, hp2); FFMA2(acc[2][1], wA.y, hp2);
            FFMA2(acc[2][2], wB.x, hp2); FFMA2(acc[2][3], wB.y, hp2);
            FFMA2(acc[3][0], wA.x, hp3); FFMA2(acc[3][1], wA.y, hp3);
            FFMA2(acc[3][2], wB.x, hp3); FFMA2(acc[3][3], wB.y, hp3);
        }

        // ============ in-warp k-reduction ==============================
        // Round A: fold slots {2,3} -> {0,1}; partner flips top q bit.
        #pragma unroll
        for (int m = 0; m < 2; ++m)
            #pragma unroll
            for (int p = 0; p < 4; ++p) {
                ull o = shfl_xor_u64(acc[m + 2][p], rdA);
                ADDF2(acc[m][p], o);
            }
        // e-swap: L1 odd slices normalize slot labels (once per step)
        #pragma unroll
        for (int p = 0; p < 4; ++p) {
            ull a = acc[0][p], b = acc[1][p];
            acc[0][p] = eswap ? b : a;
            acc[1][p] = eswap ? a : b;
        }
        // Round B (L1 only): fold slot 1 -> 0; partner flips q0 (lane bit 2)
        #pragma unroll
        for (int p = 0; p < 4; ++p) {
            ull o = shfl_xor_u64(acc[1][p], 4);
            if (isL1) ADDF2(acc[0][p], o);
        }

        // ================= elementwise (registers only) =================
        float* hw = sm + OFF_HCAT + ((t + 1) & 1) * HBUF;   // write buffer
        if (isL1 && t > 0) {
            // owns batch 4bg+q, units 2c,2c+1
            float gi0, gi1, gf0, gf1, gg0, gg1, go0, go1;
            UNPACK2(gi0, gi1, acc[0][0]);
            UNPACK2(gf0, gf1, acc[0][1]);
            UNPACK2(gg0, gg1, acc[0][2]);
            UNPACK2(go0, go1, acc[0][3]);
            float c0 = fmaf(sigf(gf0), cst[0], sigf(gi0) * tanh_fast(gg0));
            float c1 = fmaf(sigf(gf1), cst[1], sigf(gi1) * tanh_fast(gg1));
            cst[0] = c0; cst[1] = c1;
            int boff = 4 * bg + q;
            hw[hrow0 + boff] = sigf(go0) * tanh_fast(c0);
            hw[hrow1 + boff] = sigf(go1) * tanh_fast(c1);
        }
        if (isL0 && t < T_LEN) {
            // owns batches 4bg+2q, 4bg+2q+1 (slots 0,1), units 2c,2c+1
            float h0[2], h1[2];
            #pragma unroll
            for (int s = 0; s < 2; ++s) {
                float gi0, gi1, gf0, gf1, gg0, gg1, go0, go1;
                UNPACK2(gi0, gi1, acc[s][0]);
                UNPACK2(gf0, gf1, acc[s][1]);
                UNPACK2(gg0, gg1, acc[s][2]);
                UNPACK2(go0, go1, acc[s][3]);
                float c0 = fmaf(sigf(gf0), cst[2 * s],     sigf(gi0) * tanh_fast(gg0));
                float c1 = fmaf(sigf(gf1), cst[2 * s + 1], sigf(gi1) * tanh_fast(gg1));
                cst[2 * s] = c0; cst[2 * s + 1] = c1;
                h0[s] = sigf(go0) * tanh_fast(c0);
                h1[s] = sigf(go1) * tanh_fast(c1);
            }
            int boff = 4 * bg + 2 * q;
            *(float2*)(hw + hrow0 + boff) = make_float2(h0[0], h0[1]);
            *(float2*)(hw + hrow1 + boff) = make_float2(h1[0], h1[1]);
        }
        __syncthreads();
    }

    // ================= final classifier on h2[T-1] =================
    const float* hf = sm + OFF_HCAT + ((T_LEN + 1) & 1) * HBUF;
    if (tid < GB * 2) {
        int bb = tid >> 1, cls = tid & 1;
        float acc2 = bfc[cls];
        #pragma unroll
        for (int k = 0; k < HH; ++k)
            acc2 = fmaf(Wfc[cls * HH + k], hf[(HH + k) * HS + bb], acc2);
        out[(b0 + bb) * 2 + cls] = acc2;
    }
}

extern "C" void kernel_launch(void* const* d_in, const int* in_sizes, int n_in,
                              void* d_out, int out_size)
{
    const float* x    = (const float*)d_in[0];
    const float* Wih0 = (const float*)d_in[1];
    const float* Whh0 = (const float*)d_in[2];
    const float* bih0 = (const float*)d_in[3];
    const float* bhh0 = (const float*)d_in[4];
    const float* Wih1 = (const float*)d_in[5];
    const float* Whh1 = (const float*)d_in[6];
    const float* bih1 = (const float*)d_in[7];
    const float* bhh1 = (const float*)d_in[8];
    const float* Wfc  = (const float*)d_in[9];
    const float* bfc  = (const float*)d_in[10];
    float* out = (float*)d_out;

    cudaFuncSetAttribute(lstm2_kernel,
                         cudaFuncAttributeMaxDynamicSharedMemorySize, SMEM_BYTES);
    lstm2_kernel<<<NCTA, NTHR, SMEM_BYTES>>>(
        x, Wih0, Whh0, bih0, bhh0, Wih1, Whh1, bih1, bhh1, Wfc, bfc, out);
}